// round 17
// baseline (speedup 1.0000x reference)
#include <cuda_runtime.h>

#define NN 50000
#define DD 128
#define EE 800000
#define LN_EPS 1e-5f
#define FULLM 0xFFFFFFFFu
#define PAD 64          // max degree (Poisson mean 16; P(>64) ~ 1e-20)
#define WT_S 132
#define SMEM_BYTES (WT_S * 128 * 4)
#define NT32 1563       // ceil(50000 / 32)

// Persistent scratch
__device__ int    g_cnt[NN];                 // zeroed at module load; re-zeroed in gather phase
__device__ float2 g_slot[(size_t)NN * PAD];  // {col_bits, val}
__device__ float  g_t[(size_t)NN * DD];      // t = x @ W^T
__device__ int    g_bar;                     // monotonic barrier counter (never reset)

__global__ __launch_bounds__(256) void fused_all(
    const float* __restrict__ x,
    const float* __restrict__ ev,
    const float* __restrict__ W,
    const float* __restrict__ bvec,
    const float* __restrict__ gamma,
    const float* __restrict__ beta,
    const int*   __restrict__ er,
    const int*   __restrict__ ec,
    float* __restrict__ out) {
    extern __shared__ float Wt[];  // [128 k][132] : Wt[k*132+c] = W[c][k]

    const int t    = threadIdx.x;
    const int lane = t & 31;
    const int wid  = t >> 5;
    const int nblk = gridDim.x;

    // ---------------- Phase 1: bucket scatter (grid-stride over edges) ----
    {
        const int stride = nblk * 256;
        for (int e = blockIdx.x * 256 + t; e < EE; e += stride) {
            int   r = __ldg(er + e);
            int   c = __ldg(ec + e);
            float v = __ldg(ev + e);
            int   p = atomicAdd(&g_cnt[r], 1);
            g_slot[(size_t)r * PAD + p] = make_float2(__int_as_float(c), v);
        }
    }

    // ---------------- Phase 2: transform GEMM  t = x @ W^T ---------------
    for (int idx = t; idx < 128 * 128; idx += 256) {
        int c = idx >> 7;
        int k = idx & 127;
        Wt[k * WT_S + c] = W[idx];
    }
    __syncthreads();

    const int c0 = 4 * lane;
    for (int tile = blockIdx.x; tile < NT32; tile += nblk) {
        const int row0 = tile * 32 + wid * 4;
        if (row0 + 4 > NN) continue;  // partial last tile: whole warps skip
        const float* sr = x + (size_t)row0 * DD;

        float acc[4][4];
#pragma unroll
        for (int r = 0; r < 4; r++)
            acc[r][0] = acc[r][1] = acc[r][2] = acc[r][3] = 0.f;

        float sA = __ldg(sr + lane);
        float sB = __ldg(sr + 128 + lane);
        float sC = __ldg(sr + 256 + lane);
        float sD = __ldg(sr + 384 + lane);

#pragma unroll
        for (int g = 0; g < 4; g++) {
            const int k0 = g * 32;
            float nA = 0.f, nB = 0.f, nC = 0.f, nD = 0.f;
            if (g < 3) {
                nA = __ldg(sr + k0 + 32 + lane);
                nB = __ldg(sr + 128 + k0 + 32 + lane);
                nC = __ldg(sr + 256 + k0 + 32 + lane);
                nD = __ldg(sr + 384 + k0 + 32 + lane);
            }
#pragma unroll
            for (int j = 0; j < 32; j++) {
                float v0 = __shfl_sync(FULLM, sA, j);
                float v1 = __shfl_sync(FULLM, sB, j);
                float v2 = __shfl_sync(FULLM, sC, j);
                float v3 = __shfl_sync(FULLM, sD, j);
                float4 wv = *(const float4*)&Wt[(k0 + j) * WT_S + c0];
                acc[0][0] = fmaf(v0, wv.x, acc[0][0]);
                acc[0][1] = fmaf(v0, wv.y, acc[0][1]);
                acc[0][2] = fmaf(v0, wv.z, acc[0][2]);
                acc[0][3] = fmaf(v0, wv.w, acc[0][3]);
                acc[1][0] = fmaf(v1, wv.x, acc[1][0]);
                acc[1][1] = fmaf(v1, wv.y, acc[1][1]);
                acc[1][2] = fmaf(v1, wv.z, acc[1][2]);
                acc[1][3] = fmaf(v1, wv.w, acc[1][3]);
                acc[2][0] = fmaf(v2, wv.x, acc[2][0]);
                acc[2][1] = fmaf(v2, wv.y, acc[2][1]);
                acc[2][2] = fmaf(v2, wv.z, acc[2][2]);
                acc[2][3] = fmaf(v2, wv.w, acc[2][3]);
                acc[3][0] = fmaf(v3, wv.x, acc[3][0]);
                acc[3][1] = fmaf(v3, wv.y, acc[3][1]);
                acc[3][2] = fmaf(v3, wv.z, acc[3][2]);
                acc[3][3] = fmaf(v3, wv.w, acc[3][3]);
            }
            sA = nA; sB = nB; sC = nC; sD = nD;
        }

#pragma unroll
        for (int r = 0; r < 4; r++) {
            float4 y = make_float4(acc[r][0], acc[r][1], acc[r][2], acc[r][3]);
            ((float4*)g_t)[(size_t)(row0 + r) * 32 + lane] = y;
        }
    }

    // ---------------- Phase 3: device-wide barrier ------------------------
    // Monotonic counter: launches are serialized, each adds exactly nblk
    // arrivals, so epoch = pos / nblk is launch-local. No reset needed.
    __threadfence();
    __syncthreads();
    if (t == 0) {
        int pos    = atomicAdd(&g_bar, 1);
        int target = (pos / nblk + 1) * nblk;
        while (*(volatile int*)&g_bar < target) __nanosleep(64);
    }
    __syncthreads();
    __threadfence();

    // ---------------- Phase 4: gather + bias + LayerNorm + ReLU ----------
    const float4 bias = ((const float4*)bvec)[lane];
    const float4 gmv  = ((const float4*)gamma)[lane];
    const float4 btv  = ((const float4*)beta)[lane];
    const int wglob = blockIdx.x * 8 + wid;
    const int wtot  = nblk * 8;

    for (int row = wglob; row < NN; row += wtot) {
        int deg = 0;
        if (lane == 0) {
            deg = g_cnt[row];
            g_cnt[row] = 0;  // restore invariant for next replay
        }
        deg = __shfl_sync(FULLM, deg, 0);

        const float2* bucket = g_slot + (size_t)row * PAD;
        float4 acc = make_float4(0.f, 0.f, 0.f, 0.f);

        for (int gb = 0; gb < deg; gb += 32) {
            const int n = min(32, deg - gb);
            int   cc = 0;
            float vv = 0.f;
            if (gb + lane < deg) {
                float2 sv = bucket[gb + lane];   // plain load (written this launch)
                cc = __float_as_int(sv.x);
                vv = sv.y;
            }
            int j = 0;
            for (; j + 4 <= n; j += 4) {
                int   c0i = __shfl_sync(FULLM, cc, j);
                int   c1i = __shfl_sync(FULLM, cc, j + 1);
                int   c2i = __shfl_sync(FULLM, cc, j + 2);
                int   c3i = __shfl_sync(FULLM, cc, j + 3);
                float v0 = __shfl_sync(FULLM, vv, j);
                float v1 = __shfl_sync(FULLM, vv, j + 1);
                float v2 = __shfl_sync(FULLM, vv, j + 2);
                float v3 = __shfl_sync(FULLM, vv, j + 3);
                float4 x0 = ((const float4*)g_t)[(size_t)c0i * 32 + lane];
                float4 x1 = ((const float4*)g_t)[(size_t)c1i * 32 + lane];
                float4 x2 = ((const float4*)g_t)[(size_t)c2i * 32 + lane];
                float4 x3 = ((const float4*)g_t)[(size_t)c3i * 32 + lane];
                acc.x = fmaf(v0, x0.x, acc.x); acc.y = fmaf(v0, x0.y, acc.y);
                acc.z = fmaf(v0, x0.z, acc.z); acc.w = fmaf(v0, x0.w, acc.w);
                acc.x = fmaf(v1, x1.x, acc.x); acc.y = fmaf(v1, x1.y, acc.y);
                acc.z = fmaf(v1, x1.z, acc.z); acc.w = fmaf(v1, x1.w, acc.w);
                acc.x = fmaf(v2, x2.x, acc.x); acc.y = fmaf(v2, x2.y, acc.y);
                acc.z = fmaf(v2, x2.z, acc.z); acc.w = fmaf(v2, x2.w, acc.w);
                acc.x = fmaf(v3, x3.x, acc.x); acc.y = fmaf(v3, x3.y, acc.y);
                acc.z = fmaf(v3, x3.z, acc.z); acc.w = fmaf(v3, x3.w, acc.w);
            }
            for (; j < n; j++) {
                int   ci = __shfl_sync(FULLM, cc, j);
                float vj = __shfl_sync(FULLM, vv, j);
                float4 x0 = ((const float4*)g_t)[(size_t)ci * 32 + lane];
                acc.x = fmaf(vj, x0.x, acc.x); acc.y = fmaf(vj, x0.y, acc.y);
                acc.z = fmaf(vj, x0.z, acc.z); acc.w = fmaf(vj, x0.w, acc.w);
            }
        }

        acc.x += bias.x; acc.y += bias.y; acc.z += bias.z; acc.w += bias.w;

        float s = acc.x + acc.y + acc.z + acc.w;
        float q = acc.x * acc.x + acc.y * acc.y + acc.z * acc.z + acc.w * acc.w;
#pragma unroll
        for (int o = 16; o > 0; o >>= 1) {
            s += __shfl_xor_sync(FULLM, s, o);
            q += __shfl_xor_sync(FULLM, q, o);
        }
        const float mu   = s * (1.0f / 128.0f);
        const float var  = q * (1.0f / 128.0f) - mu * mu;
        const float rstd = rsqrtf(var + LN_EPS);

        float4 y;
        y.x = fmaxf((acc.x - mu) * rstd * gmv.x + btv.x, 0.f);
        y.y = fmaxf((acc.y - mu) * rstd * gmv.y + btv.y, 0.f);
        y.z = fmaxf((acc.z - mu) * rstd * gmv.z + btv.z, 0.f);
        y.w = fmaxf((acc.w - mu) * rstd * gmv.w + btv.w, 0.f);
        ((float4*)out)[(size_t)row * 32 + lane] = y;
    }
}

// ---------------------------------------------------------------------------
extern "C" void kernel_launch(void* const* d_in, const int* in_sizes, int n_in,
                              void* d_out, int out_size) {
    const float* x     = (const float*)d_in[0];
    const float* ev    = (const float*)d_in[1];
    const float* W     = (const float*)d_in[2];
    const float* b     = (const float*)d_in[3];
    const float* gamma = (const float*)d_in[4];
    const float* beta  = (const float*)d_in[5];
    const int*   er    = (const int*)d_in[6];
    const int*   ec    = (const int*)d_in[7];
    float* out = (float*)d_out;

    (void)in_sizes; (void)n_in; (void)out_size;

    cudaFuncSetAttribute(fused_all,
                         cudaFuncAttributeMaxDynamicSharedMemorySize,
                         SMEM_BYTES);

    // Grid sized for guaranteed co-residency (software barrier safety).
    int dev = 0;
    cudaGetDevice(&dev);
    int nsm = 0;
    cudaDeviceGetAttribute(&nsm, cudaDevAttrMultiProcessorCount, dev);
    int occ = 0;
    cudaOccupancyMaxActiveBlocksPerMultiprocessor(&occ, fused_all, 256,
                                                  SMEM_BYTES);
    if (occ < 1) occ = 1;  // defensive; smem fits 3 blocks/SM by construction
    int nblk = nsm * occ;

    fused_all<<<nblk, 256, SMEM_BYTES>>>(x, ev, W, b, gamma, beta, er, ec, out);
}